// round 1
// baseline (speedup 1.0000x reference)
#include <cuda_runtime.h>
#include <cstdint>
#include <cstddef>

#define TL 512
#define NB 2048
#define FULL 0xffffffffu

// h_seq scratch: T * B * H floats = 512*2048*16 = 16M floats = 64 MiB
__device__ float g_hseq[(size_t)TL * NB * 16];

__device__ __forceinline__ float sigf(float x){
  return __fdividef(1.f, 1.f + __expf(-x));
}
__device__ __forceinline__ float tanh_fast(float x){
  return __fdividef(2.f, 1.f + __expf(-2.f * x)) - 1.f;
}

__device__ __forceinline__ void ldv16(const float* p, float v[16]){
  #pragma unroll
  for (int i = 0; i < 4; i++){
    float4 q = reinterpret_cast<const float4*>(p)[i];
    v[4*i+0] = q.x; v[4*i+1] = q.y; v[4*i+2] = q.z; v[4*i+3] = q.w;
  }
}
__device__ __forceinline__ void ldv8(const float* p, float v[8]){
  #pragma unroll
  for (int i = 0; i < 2; i++){
    float4 q = reinterpret_cast<const float4*>(p)[i];
    v[4*i+0] = q.x; v[4*i+1] = q.y; v[4*i+2] = q.z; v[4*i+3] = q.w;
  }
}

__device__ __forceinline__ float dot16(const float w[16], const float v[16]){
  float a0 = 0.f, a1 = 0.f, a2 = 0.f, a3 = 0.f;
  #pragma unroll
  for (int j = 0; j < 4; j++){
    a0 = fmaf(w[4*j+0], v[4*j+0], a0);
    a1 = fmaf(w[4*j+1], v[4*j+1], a1);
    a2 = fmaf(w[4*j+2], v[4*j+2], a2);
    a3 = fmaf(w[4*j+3], v[4*j+3], a3);
  }
  return (a0 + a1) + (a2 + a3);
}
__device__ __forceinline__ float dot8(const float w[8], const float v[8]){
  float a0 = 0.f, a1 = 0.f;
  #pragma unroll
  for (int j = 0; j < 4; j++){
    a0 = fmaf(w[2*j+0], v[2*j+0], a0);
    a1 = fmaf(w[2*j+1], v[2*j+1], a1);
  }
  return a0 + a1;
}

// ============================================================================
// Phase 1: backward LSTM scan. One warp per batch element.
// Gate rows (PyTorch order i,f,g,o = rows 0..63): lane l owns rows l and l+32.
//   lanes 0-15 : i[k], g[k]   (k = l)
//   lanes 16-31: f[k], o[k]   (k = l-16)
// h (16 floats) staged in per-warp shared memory each step.
// ============================================================================
__global__ __launch_bounds__(64)
void lstm_bwd_kernel(const float* __restrict__ x,
                     const float* __restrict__ Wih,
                     const float* __restrict__ Whh,
                     const float* __restrict__ bih,
                     const float* __restrict__ bhh)
{
  const int l = threadIdx.x & 31;
  const int w = threadIdx.x >> 5;
  const int b = blockIdx.x * 2 + w;

  __shared__ __align__(16) float sH[2][16];
  float* hbuf = sH[w];

  const int r0 = l, r1 = l + 32;
  float w0[16], w1[16];
  #pragma unroll
  for (int j = 0; j < 16; j++){ w0[j] = Whh[r0*16 + j]; w1[j] = Whh[r1*16 + j]; }
  const float wx0 = Wih[r0], wx1 = Wih[r1];
  const float b0 = bih[r0] + bhh[r0];
  const float b1 = bih[r1] + bhh[r1];

  if (l < 16) hbuf[l] = 0.f;
  float c = 0.f;
  __syncwarp();

  const float* xb = x + b;
  float* hout = g_hseq + (size_t)b * 16;

  for (int t = TL - 1; t >= 0; --t){
    float xt = __ldg(xb + (size_t)t * NB);
    float hv[16]; ldv16(hbuf, hv);

    float a0 = fmaf(xt, wx0, b0);
    float a1 = fmaf(xt, wx1, b1);
    a0 += dot16(w0, hv);
    a1 += dot16(w1, hv);

    float p, q = 0.f;
    if (l < 16) { p = sigf(a0) * tanh_fast(a1); }     // sig(i)*tanh(g)
    else        { p = sigf(a0); q = sigf(a1); }       // sig(f), sig(o)
    float pf = __shfl_xor_sync(FULL, p, 16);          // lanes<16 get sig(f)
    float qo = __shfl_xor_sync(FULL, q, 16);          // lanes<16 get sig(o)
    __syncwarp();                                     // all reads of hbuf done
    if (l < 16){
      c = fmaf(pf, c, p);                             // c = sig(f)*c + sig(i)*tanh(g)
      float hn = qo * tanh_fast(c);                   // h = sig(o)*tanh(c)
      hbuf[l] = hn;
      hout[(size_t)t * (NB * 16) + l] = hn;
    }
    __syncwarp();
  }
}

// ============================================================================
// Phase 2: forward DKF scan + fused decoder + transition. One warp per batch.
// Per-warp smem: SA[16] (a1), SB[8] (g), SC[16] (e1), SZ[16] (z), ST[16] (t1/d1)
// Output layout per (t,b): [mu_x(1), logvar_x(1), mu_z(16), logvar_z(16),
//                           mu_tr(16), logvar_tr(16)] = 66 floats.
// ============================================================================
__global__ __launch_bounds__(64)
void dkf_kernel(const float* __restrict__ eps,
                const float* __restrict__ cW1, const float* __restrict__ cb1,
                const float* __restrict__ cW2, const float* __restrict__ cb2,
                const float* __restrict__ eW1, const float* __restrict__ eb1,
                const float* __restrict__ eW2, const float* __restrict__ eb2,
                const float* __restrict__ dW1, const float* __restrict__ db1,
                const float* __restrict__ dW2, const float* __restrict__ db2,
                const float* __restrict__ tW1, const float* __restrict__ tb1,
                const float* __restrict__ tW2, const float* __restrict__ tb2,
                float* __restrict__ out)
{
  const int l = threadIdx.x & 31;
  const int w = threadIdx.x >> 5;
  const int b = blockIdx.x * 2 + w;
  const int lo = l & 15, half = l >> 4;

  __shared__ __align__(16) float sm[2][80];
  float* SA = &sm[w][0];    // 16 floats, 16B aligned
  float* SB = &sm[w][16];   // 8
  float* SC = &sm[w][24];   // 16
  float* SZ = &sm[w][40];   // 16
  float* ST = &sm[w][56];   // 16

  // ---- weights in registers (per-lane row ownership) ----
  // comb1 (16x32): pair (lo, lo+16); lane<16: h-cols, lane>=16: z-cols
  float wA[16];
  #pragma unroll
  for (int j = 0; j < 16; j++) wA[j] = cW1[lo*32 + half*16 + j];
  const float bA = cb1[lo];
  // comb2 (8x16): pair (l, l+8) over halves of a1
  const int rB = l & 7, hB = (l >> 3) & 1;
  float wB[8];
  #pragma unroll
  for (int j = 0; j < 8; j++) wB[j] = cW2[rB*16 + hB*8 + j];
  const float bB = cb2[rB];
  // enc1 (16x8): lane lo owns full row
  float wC[8];
  #pragma unroll
  for (int j = 0; j < 8; j++) wC[j] = eW1[lo*8 + j];
  const float bC = eb1[lo];
  // enc2 (32x16): lane l owns full row
  float wD[16];
  #pragma unroll
  for (int j = 0; j < 16; j++) wD[j] = eW2[l*16 + j];
  const float bD = eb2[l];
  // tr1 (16x16): pair (lo, lo+16) over halves of z_prev
  float wT1[8];
  #pragma unroll
  for (int j = 0; j < 8; j++) wT1[j] = tW1[lo*16 + half*8 + j];
  const float bT1 = tb1[lo];
  // tr2 (32x16): lane l owns full row
  float wT2[16];
  #pragma unroll
  for (int j = 0; j < 16; j++) wT2[j] = tW2[l*16 + j];
  const float bT2 = tb2[l];
  // dec1 (16x16): pair (lo, lo+16) over halves of z
  float wD1[8];
  #pragma unroll
  for (int j = 0; j < 8; j++) wD1[j] = dW1[lo*16 + half*8 + j];
  const float bD1 = db1[lo];
  // dec2 (2x16): pairs (0,2),(1,3) over halves of d1
  const int rD2 = l & 1, hD2 = (l >> 1) & 1;
  float wD2[8];
  #pragma unroll
  for (int j = 0; j < 8; j++) wD2[j] = dW2[rD2*16 + hD2*8 + j];
  const float bD2 = db2[rD2];

  if (l < 16) SZ[lo] = 0.f;      // z0 = 0
  __syncwarp();

  const float* hbase = g_hseq + (size_t)b * 16;
  const float* ebase = eps + (size_t)b * 16;
  float* obase = out + (size_t)b * 66;

  for (int t = 0; t < TL; ++t){
    const float* hp = hbase + (size_t)t * (NB * 16);
    float epsv = 0.f;
    if (l < 16) epsv = __ldg(ebase + (size_t)t * (NB * 16) + lo);
    float* outp = obase + (size_t)t * (NB * 66);

    // ---- Layer A: a1 = tanh(comb_W1 @ [h; z_prev] + b1) ----
    float in16[16];
    if (half == 0) ldv16(hp, in16);     // h part (global, broadcast)
    else           ldv16(SZ, in16);     // z_prev part
    float accA = (half == 0) ? bA : 0.f;
    accA += dot16(wA, in16);
    accA += __shfl_xor_sync(FULL, accA, 16);
    float a1 = tanh_fast(accA);
    __syncwarp();
    if (l < 16) SA[lo] = a1;
    __syncwarp();

    // ---- Layer B: g = comb_W2 @ a1 + b2 ----
    float av[8]; ldv8(SA + hB*8, av);
    float accB = (l < 8) ? bB : 0.f;
    accB += dot8(wB, av);
    accB += __shfl_xor_sync(FULL, accB, 8);
    __syncwarp();
    if (l < 8) SB[l] = accB;
    __syncwarp();

    // ---- Layer C: e1 = tanh(enc_W1 @ g + eb1) ----
    float gv[8]; ldv8(SB, gv);
    float e1 = tanh_fast(bC + dot8(wC, gv));
    if (l < 16) SC[lo] = e1;

    // ---- Layer T1: t1 = tanh(tr_W1 @ z_prev + tb1)  (SZ still z_prev) ----
    float zpv[8]; ldv8(SZ + half*8, zpv);
    float accT = (half == 0) ? bT1 : 0.f;
    accT += dot8(wT1, zpv);
    accT += __shfl_xor_sync(FULL, accT, 16);
    float t1 = tanh_fast(accT);
    __syncwarp();                       // SC visible; all SZ(z_prev) reads done
    if (l < 16) ST[lo] = t1;

    // ---- Layer D: e2 = enc_W2 @ e1 + eb2 ; sample z ----
    float ev[16]; ldv16(SC, ev);
    float e2 = bD + dot16(wD, ev);
    outp[2 + l] = e2;                   // mu_z (lanes<16), logvar_z (lanes>=16)
    float lvz = __shfl_xor_sync(FULL, e2, 16);     // lanes<16 get logvar
    float znew = fmaf(epsv, __expf(0.5f * lvz), e2);
    __syncwarp();                       // ST(t1) visible; SZ safe to overwrite
    if (l < 16) SZ[lo] = znew;

    // ---- Layer T2: tr = tr_W2 @ t1 + tb2 ----
    float tv[16]; ldv16(ST, tv);
    float r2 = bT2 + dot16(wT2, tv);
    outp[34 + l] = r2;                  // mu_tr / logvar_tr
    __syncwarp();                       // SZ(z) visible; ST reads done

    // ---- Layer D1: d1 = tanh(dec_W1 @ z + db1) ----
    float znv[8]; ldv8(SZ + half*8, znv);
    float accD1 = (half == 0) ? bD1 : 0.f;
    accD1 += dot8(wD1, znv);
    accD1 += __shfl_xor_sync(FULL, accD1, 16);
    float d1 = tanh_fast(accD1);
    if (l < 16) ST[lo] = d1;
    __syncwarp();

    // ---- Layer D2: d = dec_W2 @ d1 + db2 ----
    float dv[8]; ldv8(ST + hD2*8, dv);
    float accD2 = (l < 2) ? bD2 : 0.f;
    accD2 += dot8(wD2, dv);
    accD2 += __shfl_xor_sync(FULL, accD2, 2);
    if (l < 2) outp[l] = accD2;         // mu_x, logvar_x
  }
}

extern "C" void kernel_launch(void* const* d_in, const int* in_sizes, int n_in,
                              void* d_out, int out_size)
{
  const float* x   = (const float*)d_in[0];
  const float* eps = (const float*)d_in[1];
  const float* Wih = (const float*)d_in[2];
  const float* Whh = (const float*)d_in[3];
  const float* bih = (const float*)d_in[4];
  const float* bhh = (const float*)d_in[5];
  const float* cW1 = (const float*)d_in[6];
  const float* cb1 = (const float*)d_in[7];
  const float* cW2 = (const float*)d_in[8];
  const float* cb2 = (const float*)d_in[9];
  const float* eW1 = (const float*)d_in[10];
  const float* eb1 = (const float*)d_in[11];
  const float* eW2 = (const float*)d_in[12];
  const float* eb2 = (const float*)d_in[13];
  const float* dW1 = (const float*)d_in[14];
  const float* db1 = (const float*)d_in[15];
  const float* dW2 = (const float*)d_in[16];
  const float* db2 = (const float*)d_in[17];
  const float* tW1 = (const float*)d_in[18];
  const float* tb1 = (const float*)d_in[19];
  const float* tW2 = (const float*)d_in[20];
  const float* tb2 = (const float*)d_in[21];
  float* out = (float*)d_out;

  lstm_bwd_kernel<<<NB/2, 64>>>(x, Wih, Whh, bih, bhh);
  dkf_kernel<<<NB/2, 64>>>(eps, cW1, cb1, cW2, cb2, eW1, eb1, eW2, eb2,
                           dW1, db1, dW2, db2, tW1, tb1, tW2, tb2, out);
}